// round 4
// baseline (speedup 1.0000x reference)
#include <cuda_runtime.h>
#include <stdint.h>

#define NUM_TNETS 8388608
#define NUM_NODES 1048576

// 4 tnets per thread: 2x int4 pin loads (8 pins), 1x float4 weight load.
// Streaming loads use evict-first (.cs); random gathers bypass L1 (.cg).
// Binding resource is REDG lane throughput (~1.29 cyc/lane spread), so the
// goal is simply to keep atomic issue slots saturated.
__global__ void __launch_bounds__(256) scatter_add_kernel(
    const float* __restrict__ beta,          // [1]
    const float* __restrict__ tnet_weights,  // [NUM_TNETS]
    const int*   __restrict__ flat_tnet2pin, // [2*NUM_TNETS] int32
    const int*   __restrict__ pin2node,      // [NUM_PINS]    int32
    float* __restrict__ out)                 // [NUM_NODES]
{
    int q = blockIdx.x * blockDim.x + threadIdx.x;  // quad index: 4 tnets each

    // pins of four arcs: [s0,d0,s1,d1] and [s2,d2,s3,d3]
    const int4* p4 = reinterpret_cast<const int4*>(flat_tnet2pin);
    int4 pA = __ldcs(p4 + 2 * q);
    int4 pB = __ldcs(p4 + 2 * q + 1);

    // four arc weights
    float4 wv = __ldcs(reinterpret_cast<const float4*>(tnet_weights) + q);

    float b = __ldg(beta);
    float w0 = wv.x * b;
    float w1 = wv.y * b;
    float w2 = wv.z * b;
    float w3 = wv.w * b;

    // eight independent random gathers (MLP=8), L1-bypass
    int n0 = __ldcg(pin2node + pA.x);
    int n1 = __ldcg(pin2node + pA.y);
    int n2 = __ldcg(pin2node + pA.z);
    int n3 = __ldcg(pin2node + pA.w);
    int n4 = __ldcg(pin2node + pB.x);
    int n5 = __ldcg(pin2node + pB.y);
    int n6 = __ldcg(pin2node + pB.z);
    int n7 = __ldcg(pin2node + pB.w);

    atomicAdd(out + n0, w0);
    atomicAdd(out + n1, w0);
    atomicAdd(out + n2, w1);
    atomicAdd(out + n3, w1);
    atomicAdd(out + n4, w2);
    atomicAdd(out + n5, w2);
    atomicAdd(out + n6, w3);
    atomicAdd(out + n7, w3);
}

extern "C" void kernel_launch(void* const* d_in, const int* in_sizes, int n_in,
                              void* d_out, int out_size) {
    const float* beta         = (const float*)d_in[0];
    const float* tnet_weights = (const float*)d_in[1];
    const int*   flat_t2p     = (const int*)d_in[2];
    const int*   pin2node     = (const int*)d_in[3];
    float* out = (float*)d_out;

    // 1) zero the poisoned output
    cudaMemsetAsync(out, 0, (size_t)out_size * sizeof(float));

    // 2) gather + atomic scatter-add, beta folded in
    {
        const int threads = 256;
        const int quads = NUM_TNETS / 4;              // 2,097,152
        const int blocks = quads / threads;           // 8192 exact
        scatter_add_kernel<<<blocks, threads>>>(beta, tnet_weights, flat_t2p,
                                                pin2node, out);
    }
}

// round 5
// speedup vs baseline: 1.0227x; 1.0227x over previous
#include <cuda_runtime.h>
#include <stdint.h>

#define NUM_TNETS 8388608
#define NUM_NODES 1048576

// 2 tnets per thread (best measured shape): int4 pins + float2 weights.
// Streaming loads: evict-first (.cs). Random gathers: L2-only (.cg) — ~0% L1
// hit rate on random 4B over an 84MB table, so L1 allocation is pure waste.
// Binding resource: LTS transaction throughput (~53M txns / 184 LTS).
__global__ void __launch_bounds__(256) scatter_add_kernel(
    const float* __restrict__ beta,          // [1]
    const float* __restrict__ tnet_weights,  // [NUM_TNETS]
    const int*   __restrict__ flat_tnet2pin, // [2*NUM_TNETS] int32
    const int*   __restrict__ pin2node,      // [NUM_PINS]    int32
    float* __restrict__ out)                 // [NUM_NODES]
{
    int t = blockIdx.x * blockDim.x + threadIdx.x;  // pair index: 2 tnets each

    // coalesced 16B streaming load: pins of two arcs [s0,d0,s1,d1]
    int4 pins = __ldcs(reinterpret_cast<const int4*>(flat_tnet2pin) + t);
    // coalesced 8B streaming load: the two arc weights
    float2 wv = __ldcs(reinterpret_cast<const float2*>(tnet_weights) + t);

    float b = __ldg(beta);
    float w0 = wv.x * b;
    float w1 = wv.y * b;

    // four independent random gathers (MLP=4), L2-only
    int n0 = __ldcg(pin2node + pins.x);
    int n1 = __ldcg(pin2node + pins.y);
    int n2 = __ldcg(pin2node + pins.z);
    int n3 = __ldcg(pin2node + pins.w);

    atomicAdd(out + n0, w0);
    atomicAdd(out + n1, w0);
    atomicAdd(out + n2, w1);
    atomicAdd(out + n3, w1);
}

extern "C" void kernel_launch(void* const* d_in, const int* in_sizes, int n_in,
                              void* d_out, int out_size) {
    const float* beta         = (const float*)d_in[0];
    const float* tnet_weights = (const float*)d_in[1];
    const int*   flat_t2p     = (const int*)d_in[2];
    const int*   pin2node     = (const int*)d_in[3];
    float* out = (float*)d_out;

    // 1) zero the poisoned output
    cudaMemsetAsync(out, 0, (size_t)out_size * sizeof(float));

    // 2) gather + atomic scatter-add, beta folded in
    {
        const int threads = 256;
        const int pairs = NUM_TNETS / 2;          // 4,194,304
        const int blocks = pairs / threads;       // 16384 exact
        scatter_add_kernel<<<blocks, threads>>>(beta, tnet_weights, flat_t2p,
                                                pin2node, out);
    }
}